// round 16
// baseline (speedup 1.0000x reference)
#include <cuda_runtime.h>
#include <cstdint>
#include <cfloat>

// Sparsemax (d = 4096), max-seeded Michelot with sparse scatter epilogue.
//
//   Output is >99% zeros (support ~10-30 / 4096), and zeros don't depend
//   on tau. So: issue the row loads, then immediately blanket-store zeros
//   (no dependency). Compute tau as before (block max seed M-1, compact
//   ~16 (value,index) candidates, warp-0 register Michelot), then warp 0
//   scatters val - tau to the few support indices. The __syncthreads
//   between the zero stores and the scatter orders the overwrites.
//
//   No barrier 3, no epilogue row re-read: the DRAM write stream starts at
//   CTA begin and the CTA retires right after the tiny scatter.

#define ROW_D     4096
#define THREADS   256
#define NW        (THREADS / 32)
#define V4_PER_T  4
#define CAND_MAX  512

__device__ __forceinline__ unsigned f2key(float f) {
    const unsigned b = __float_as_uint(f);
    return b ^ ((unsigned)((int)b >> 31) | 0x80000000u);
}
__device__ __forceinline__ float key2f(unsigned k) {
    return __uint_as_float(k ^ ((unsigned)((int)(~k) >> 31) | 0x80000000u));
}

__global__ __launch_bounds__(THREADS, 8)
void sparsemax_kernel(const float* __restrict__ x, float* __restrict__ out)
{
    __shared__ float  s_max[NW];
    __shared__ int    s_n;
    __shared__ float  s_val[CAND_MAX];
    __shared__ int    s_idx[CAND_MAX];
    __shared__ float4 s_row[ROW_D / 4];   // 16 KB row stage (keeps regs at ~32)

    const size_t row_base = (size_t)blockIdx.x * ROW_D;
    const float4* __restrict__ xr  = reinterpret_cast<const float4*>(x + row_base);
    float4*       __restrict__ orr = reinterpret_cast<float4*>(out + row_base);
    float*        __restrict__ og  = out + row_base;

    const int tid = threadIdx.x;
    const int wid = tid >> 5;
    const int lid = tid & 31;

    // ---- issue row loads (front-batched MLP), then blanket zero stores ----
    float4 v[V4_PER_T];
#pragma unroll
    for (int i = 0; i < V4_PER_T; ++i)
        v[i] = __ldcs(&xr[tid + i * THREADS]);

    const float4 z4 = make_float4(0.0f, 0.0f, 0.0f, 0.0f);
#pragma unroll
    for (int i = 0; i < V4_PER_T; ++i)
        __stcs(&orr[tid + i * THREADS], z4);           // independent of tau

    // ---- pass 1: per-warp max, stash row to SMEM ----
    float m = -FLT_MAX;
#pragma unroll
    for (int i = 0; i < V4_PER_T; ++i) {
        const float4 q = v[i];
        m = fmaxf(m, fmaxf(fmaxf(q.x, q.y), fmaxf(q.z, q.w)));
        s_row[tid + i * THREADS] = q;
    }
    m = key2f(__reduce_max_sync(0xFFFFFFFFu, f2key(m)));
    if (lid == 0) s_max[wid] = m;
    if (tid == 0) s_n = 0;
    __syncthreads();                                   // barrier 1

    float M = s_max[0];
#pragma unroll
    for (int w = 1; w < NW; ++w) M = fmaxf(M, s_max[w]);
    const float thr0 = M - 1.0f;                       // <= tau*

    // ---- pass 2: compact (value, index) of survivors {x > M-1} ----
    int myc = 0;
#pragma unroll
    for (int i = 0; i < V4_PER_T; ++i) {
        const float4 q = s_row[tid + i * THREADS];
        myc += (q.x > thr0) + (q.y > thr0) + (q.z > thr0) + (q.w > thr0);
    }
    if (myc > 0) {
        int pos = atomicAdd(&s_n, myc);
#pragma unroll
        for (int i = 0; i < V4_PER_T; ++i) {
            const float4 q = s_row[tid + i * THREADS];
            const int base = (tid + i * THREADS) * 4;
            if (q.x > thr0) { if (pos < CAND_MAX) { s_val[pos] = q.x; s_idx[pos] = base + 0; } ++pos; }
            if (q.y > thr0) { if (pos < CAND_MAX) { s_val[pos] = q.y; s_idx[pos] = base + 1; } ++pos; }
            if (q.z > thr0) { if (pos < CAND_MAX) { s_val[pos] = q.z; s_idx[pos] = base + 2; } ++pos; }
            if (q.w > thr0) { if (pos < CAND_MAX) { s_val[pos] = q.w; s_idx[pos] = base + 3; } ++pos; }
        }
    }
    __syncthreads();         // barrier 2 (last): orders zero-stores vs scatter

    // ---- warp 0: Michelot over candidates, then sparse scatter ----
    // (warps 1..7 exit here; their stores are already in flight)
    if (wid == 0) {
        const int n = s_n;
        float tau  = thr0;
        int   prev = -1;

        if (n <= 32) {
            // dominant case (~16 candidates): one register per lane
            const float r0 = (lid < n) ? s_val[lid] : -FLT_MAX;
            for (int iter = 0; iter < 64; ++iter) {
                float ls = 0.0f;
                int   lc = 0;
                if (r0 > tau) { ls = r0; lc = 1; }
#pragma unroll
                for (int o = 16; o > 0; o >>= 1)
                    ls += __shfl_xor_sync(0xFFFFFFFFu, ls, o);
                lc = __reduce_add_sync(0xFFFFFFFFu, lc);
                tau = (ls - 1.0f) / (float)lc;   // lc >= 1: row max > tau
                if (lc == prev) break;           // fixed point -> tau = tau*
                prev = lc;
            }
            if (lid < n && r0 > tau) og[s_idx[lid]] = r0 - tau;
        } else if (n <= 64) {
            const float r0 = s_val[lid];
            const float r1 = (lid + 32 < n) ? s_val[lid + 32] : -FLT_MAX;
            for (int iter = 0; iter < 64; ++iter) {
                float ls = 0.0f;
                int   lc = 0;
                if (r0 > tau) { ls += r0; ++lc; }
                if (r1 > tau) { ls += r1; ++lc; }
#pragma unroll
                for (int o = 16; o > 0; o >>= 1)
                    ls += __shfl_xor_sync(0xFFFFFFFFu, ls, o);
                lc = __reduce_add_sync(0xFFFFFFFFu, lc);
                tau = (ls - 1.0f) / (float)lc;
                if (lc == prev) break;
                prev = lc;
            }
            if (r0 > tau)                og[s_idx[lid]]      = r0 - tau;
            if (lid + 32 < n && r1 > tau) og[s_idx[lid + 32]] = r1 - tau;
        } else if (n <= CAND_MAX) {
            for (int iter = 0; iter < 64; ++iter) {
                float ls = 0.0f;
                int   lc = 0;
                for (int j = lid; j < n; j += 32) {
                    const float vv = s_val[j];
                    if (vv > tau) { ls += vv; ++lc; }
                }
#pragma unroll
                for (int o = 16; o > 0; o >>= 1)
                    ls += __shfl_xor_sync(0xFFFFFFFFu, ls, o);
                lc = __reduce_add_sync(0xFFFFFFFFu, lc);
                tau = (ls - 1.0f) / (float)lc;
                if (lc == prev) break;
                prev = lc;
            }
            for (int j = lid; j < n; j += 32) {
                const float vv = s_val[j];
                if (vv > tau) og[s_idx[j]] = vv - tau;
            }
        } else {
            // degenerate fallback: full-row Michelot + full-row scatter
            const float* __restrict__ src = reinterpret_cast<const float*>(s_row);
            for (int iter = 0; iter < 64; ++iter) {
                float ls = 0.0f;
                int   lc = 0;
                for (int j = lid; j < ROW_D; j += 32) {
                    const float vv = src[j];
                    if (vv > tau) { ls += vv; ++lc; }
                }
#pragma unroll
                for (int o = 16; o > 0; o >>= 1)
                    ls += __shfl_xor_sync(0xFFFFFFFFu, ls, o);
                lc = __reduce_add_sync(0xFFFFFFFFu, lc);
                tau = (ls - 1.0f) / (float)lc;
                if (lc == prev) break;
                prev = lc;
            }
            for (int j = lid; j < ROW_D; j += 32) {
                const float vv = src[j];
                if (vv > tau) og[j] = vv - tau;
            }
        }
    }
}

extern "C" void kernel_launch(void* const* d_in, const int* in_sizes, int n_in,
                              void* d_out, int out_size)
{
    const float* x   = (const float*)d_in[0];
    float*       out = (float*)d_out;
    const int n_rows = in_sizes[0] / ROW_D;   // 16384
    sparsemax_kernel<<<n_rows, THREADS>>>(x, out);
}

// round 17
// speedup vs baseline: 1.0107x; 1.0107x over previous
#include <cuda_runtime.h>
#include <cstdint>
#include <cfloat>

// Sparsemax (d = 4096), max-seeded Michelot, row staged in SMEM (8 CTAs/SM).
// R14 structure (best measured) + survivor-mask epilogue: threads with no
// survivors (>90% of threads) store pure zeros without re-reading the row.
//
//   Pass 1: load row (streaming), per-warp max, stash row -> s_row. [bar 1]
//   Block max M; thr0 = M-1 (tau* >= M-1 => survivors superset of support).
//   Pass 2: re-read row, compact survivors -> s_buf, record per-thread
//           16-bit survivor mask.                                   [bar 2]
//   Warp 0: register-resident Michelot (n<=32 / n<=64 paths).       [bar 3]
//   Epilogue: mask==0 -> four zero float4 stores (no LDS);
//             else re-read own slots and store max(x - tau, 0).

#define ROW_D     4096
#define THREADS   256
#define NW        (THREADS / 32)
#define V4_PER_T  4
#define CAND_MAX  512

__device__ __forceinline__ unsigned f2key(float f) {
    const unsigned b = __float_as_uint(f);
    return b ^ ((unsigned)((int)b >> 31) | 0x80000000u);
}
__device__ __forceinline__ float key2f(unsigned k) {
    return __uint_as_float(k ^ ((unsigned)((int)(~k) >> 31) | 0x80000000u));
}

__global__ __launch_bounds__(THREADS, 8)
void sparsemax_kernel(const float* __restrict__ x, float* __restrict__ out)
{
    __shared__ float  s_max[NW];
    __shared__ int    s_n;
    __shared__ float  s_tau;
    __shared__ float  s_buf[CAND_MAX];
    __shared__ float4 s_row[ROW_D / 4];   // 16 KB: the whole row

    const size_t row_base = (size_t)blockIdx.x * ROW_D;
    const float4* __restrict__ xr  = reinterpret_cast<const float4*>(x + row_base);
    float4*       __restrict__ orr = reinterpret_cast<float4*>(out + row_base);

    const int tid = threadIdx.x;
    const int wid = tid >> 5;
    const int lid = tid & 31;

    // ---- pass 1: load row, track max, stash to SMEM ----
    float m = -FLT_MAX;
#pragma unroll
    for (int i = 0; i < V4_PER_T; ++i) {
        const float4 q = __ldcs(&xr[tid + i * THREADS]);
        m = fmaxf(m, fmaxf(fmaxf(q.x, q.y), fmaxf(q.z, q.w)));
        s_row[tid + i * THREADS] = q;
    }
    m = key2f(__reduce_max_sync(0xFFFFFFFFu, f2key(m)));
    if (lid == 0) s_max[wid] = m;
    if (tid == 0) s_n = 0;
    __syncthreads();                                   // barrier 1

    float M = s_max[0];
#pragma unroll
    for (int w = 1; w < NW; ++w) M = fmaxf(M, s_max[w]);
    const float thr0 = M - 1.0f;                       // <= tau*

    // ---- pass 2: compact survivors + per-thread survivor mask ----
    unsigned mask = 0u;
#pragma unroll
    for (int i = 0; i < V4_PER_T; ++i) {
        const float4 q = s_row[tid + i * THREADS];
        mask |= (q.x > thr0 ? 1u : 0u) << (i * 4 + 0);
        mask |= (q.y > thr0 ? 1u : 0u) << (i * 4 + 1);
        mask |= (q.z > thr0 ? 1u : 0u) << (i * 4 + 2);
        mask |= (q.w > thr0 ? 1u : 0u) << (i * 4 + 3);
    }
    const int myc = __popc(mask);
    if (myc > 0) {
        int pos = atomicAdd(&s_n, myc);
#pragma unroll
        for (int i = 0; i < V4_PER_T; ++i) {
            const float4 q = s_row[tid + i * THREADS];
            if (q.x > thr0) { if (pos < CAND_MAX) s_buf[pos] = q.x; ++pos; }
            if (q.y > thr0) { if (pos < CAND_MAX) s_buf[pos] = q.y; ++pos; }
            if (q.z > thr0) { if (pos < CAND_MAX) s_buf[pos] = q.z; ++pos; }
            if (q.w > thr0) { if (pos < CAND_MAX) s_buf[pos] = q.w; ++pos; }
        }
    }
    __syncthreads();                                   // barrier 2

    // ---- warp 0: Michelot over candidates ----
    if (wid == 0) {
        const int n = s_n;
        float tau  = thr0;     // first pass reproduces iter-1 over survivors
        int   prev = -1;

        if (n <= 32) {
            // dominant case (~16 candidates): one register per lane
            const float r0 = (lid < n) ? s_buf[lid] : -FLT_MAX;
            for (int iter = 0; iter < 64; ++iter) {
                float ls = 0.0f;
                int   lc = 0;
                if (r0 > tau) { ls = r0; lc = 1; }
#pragma unroll
                for (int o = 16; o > 0; o >>= 1)
                    ls += __shfl_xor_sync(0xFFFFFFFFu, ls, o);
                lc = __reduce_add_sync(0xFFFFFFFFu, lc);

                tau = (ls - 1.0f) / (float)lc;   // lc >= 1: row max > tau
                if (lc == prev) break;           // fixed point -> tau = tau*
                prev = lc;
            }
        } else if (n <= 64) {
            const float r0 = s_buf[lid];
            const float r1 = (lid + 32 < n) ? s_buf[lid + 32] : -FLT_MAX;
            for (int iter = 0; iter < 64; ++iter) {
                float ls = 0.0f;
                int   lc = 0;
                if (r0 > tau) { ls += r0; ++lc; }
                if (r1 > tau) { ls += r1; ++lc; }
#pragma unroll
                for (int o = 16; o > 0; o >>= 1)
                    ls += __shfl_xor_sync(0xFFFFFFFFu, ls, o);
                lc = __reduce_add_sync(0xFFFFFFFFu, lc);

                tau = (ls - 1.0f) / (float)lc;
                if (lc == prev) break;
                prev = lc;
            }
        } else {
            const bool overflow = (n > CAND_MAX);      // degenerate rows only
            const float* __restrict__ src = overflow
                ? reinterpret_cast<const float*>(s_row) : s_buf;
            const int nn = overflow ? ROW_D : n;

            for (int iter = 0; iter < 64; ++iter) {
                float ls = 0.0f;
                int   lc = 0;
                for (int j = lid; j < nn; j += 32) {
                    const float vv = src[j];
                    if (vv > tau) { ls += vv; ++lc; }
                }
#pragma unroll
                for (int o = 16; o > 0; o >>= 1)
                    ls += __shfl_xor_sync(0xFFFFFFFFu, ls, o);
                lc = __reduce_add_sync(0xFFFFFFFFu, lc);

                tau = (ls - 1.0f) / (float)lc;
                if (lc == prev) break;
                prev = lc;
            }
        }
        if (lid == 0) s_tau = tau;
    }
    __syncthreads();                                   // barrier 3
    const float tau = s_tau;

    // ---- epilogue: mask==0 -> pure zero stores (no LDS); else full path ----
    if (mask == 0u) {
        const float4 z4 = make_float4(0.0f, 0.0f, 0.0f, 0.0f);
#pragma unroll
        for (int i = 0; i < V4_PER_T; ++i)
            __stcs(&orr[tid + i * THREADS], z4);
    } else {
#pragma unroll
        for (int i = 0; i < V4_PER_T; ++i) {
            const float4 q = s_row[tid + i * THREADS];
            float4 o;
            o.x = fmaxf(q.x - tau, 0.0f);
            o.y = fmaxf(q.y - tau, 0.0f);
            o.z = fmaxf(q.z - tau, 0.0f);
            o.w = fmaxf(q.w - tau, 0.0f);
            __stcs(&orr[tid + i * THREADS], o);
        }
    }
}

extern "C" void kernel_launch(void* const* d_in, const int* in_sizes, int n_in,
                              void* d_out, int out_size)
{
    const float* x   = (const float*)d_in[0];
    float*       out = (float*)d_out;
    const int n_rows = in_sizes[0] / ROW_D;   // 16384
    sparsemax_kernel<<<n_rows, THREADS>>>(x, out);
}